// round 14
// baseline (speedup 1.0000x reference)
#include <cuda_runtime.h>
#include <cuda_bf16.h>
#include <cstdint>
#include <math_constants.h>

#define N_GRAPHS 4096
#define HIDDEN   256
#define STEPS    6
#define GATESD   1024   // 4*HIDDEN
#define XDIM     512    // 2*HIDDEN

// ---------------- scratch (no allocation allowed) ----------------
__device__ float g_h[N_GRAPHS * HIDDEN];
__device__ float g_c[N_GRAPHS * HIDDEN];
__device__ float g_bc[GATESD];                 // b_ih + b_hh, gate-interleaved
__device__ int   g_start[N_GRAPHS];
__device__ int   g_end[N_GRAPHS];
__device__ __nv_bfloat16 g_x_h[N_GRAPHS * XDIM],     g_x_l[N_GRAPHS * XDIM];
__device__ __nv_bfloat16 g_hdn_h[N_GRAPHS * HIDDEN], g_hdn_l[N_GRAPHS * HIDDEN];
__device__ __nv_bfloat16 g_Wc_h[GATESD * XDIM],      g_Wc_l[GATESD * XDIM];   // gate-interleaved rows
__device__ __nv_bfloat16 g_W1_h[HIDDEN * XDIM],      g_W1_l[HIDDEN * XDIM];
__device__ __nv_bfloat16 g_W2_h[HIDDEN * HIDDEN],    g_W2_l[HIDDEN * HIDDEN];

__device__ __forceinline__ void split_bf16(float v, __nv_bfloat16& h, __nv_bfloat16& l) {
    h = __float2bfloat16(v);
    l = __float2bfloat16(v - __bfloat162float(h));
}
__device__ __forceinline__ float sigf(float x) { return 1.f / (1.f + expf(-x)); }

// ---------------- fused setup: init h/c, segments, weight fold+split ----------------
__global__ void k_setup(const int* __restrict__ idx, int nn,
                        const float* __restrict__ W_ih, const float* __restrict__ W_hh,
                        const float* __restrict__ b_ih, const float* __restrict__ b_hh,
                        const float* __restrict__ W1, const float* __restrict__ W2) {
    const int i = blockIdx.x * blockDim.x + threadIdx.x;   // 524288 threads

    g_h[i] = 0.f;              g_h[i + 524288] = 0.f;
    g_c[i] = 0.f;              g_c[i + 524288] = 0.f;
    if (i < N_GRAPHS) { g_start[i] = 0; g_end[i] = 0; }
    __threadfence();

    if (i < nn) {
        const int g = idx[i];
        if ((unsigned)g < (unsigned)N_GRAPHS) {
            if (i == 0      || idx[i - 1] != g) g_start[g] = i;
            if (i == nn - 1 || idx[i + 1] != g) g_end[g]   = i + 1;
        }
    }

    {
        const int np = i >> 9;
        const int k  = i & 511;
        const int d = np >> 2, gate = np & 3;
        const int orig = gate * HIDDEN + d;
        float v = W_ih[orig * XDIM + k];
        if (k < HIDDEN) v += W_hh[orig * HIDDEN + k];
        split_bf16(v, g_Wc_h[i], g_Wc_l[i]);
    }
    if (i < GATESD) {
        const int d2 = i >> 2, g2 = i & 3;
        const int o2 = g2 * HIDDEN + d2;
        g_bc[i] = b_ih[o2] + b_hh[o2];
    }
    if (i < HIDDEN * XDIM)   split_bf16(W1[i], g_W1_h[i], g_W1_l[i]);
    if (i < HIDDEN * HIDDEN) split_bf16(W2[i], g_W2_h[i], g_W2_l[i]);
}

// ---------------- single-pass attention, depth-1 prefetch, 6 CTAs/SM ----------------
__global__ void __launch_bounds__(256, 6)
k_attention(const float* __restrict__ emb) {
    const int g    = blockIdx.x;
    const int t    = threadIdx.x;
    const int lane = t & 31;
    const int wid  = t >> 5;

    __shared__ float h_s[HIDDEN];
    __shared__ float Rall[8][HIDDEN];
    __shared__ float mw_s[8], Sw_s[8];

    h_s[t] = g_h[(size_t)g * HIDDEN + t];
    const int s  = g_start[g];
    const int en = g_end[g];
    __syncthreads();

    const float4* h4 = reinterpret_cast<const float4*>(h_s);
    const float4 hv0 = h4[lane];
    const float4 hv1 = h4[lane + 32];

    float m = -CUDART_INF_F, S = 0.f;
    float R[8] = {0.f, 0.f, 0.f, 0.f, 0.f, 0.f, 0.f, 0.f};

    int ii = s + wid;
    float4 c0, c1;
    bool have = (ii < en);
    if (have) {
        const float4* r4 = reinterpret_cast<const float4*>(emb + (size_t)ii * HIDDEN);
        c0 = r4[lane]; c1 = r4[lane + 32];
    }
    while (have) {
        const int nx = ii + 8;
        const bool hn = nx < en;
        float4 n0f, n1f;
        if (hn) {
            const float4* r4 = reinterpret_cast<const float4*>(emb + (size_t)nx * HIDDEN);
            n0f = r4[lane]; n1f = r4[lane + 32];
        }
        float d = c0.x * hv0.x + c0.y * hv0.y + c0.z * hv0.z + c0.w * hv0.w
                + c1.x * hv1.x + c1.y * hv1.y + c1.z * hv1.z + c1.w * hv1.w;
        #pragma unroll
        for (int o = 16; o > 0; o >>= 1) d += __shfl_xor_sync(0xffffffffu, d, o);
        const float nm = fmaxf(m, d);
        const float sc = __expf(m - nm);
        const float p  = __expf(d - nm);
        S = S * sc + p;
        R[0] = R[0] * sc + p * c0.x;
        R[1] = R[1] * sc + p * c0.y;
        R[2] = R[2] * sc + p * c0.z;
        R[3] = R[3] * sc + p * c0.w;
        R[4] = R[4] * sc + p * c1.x;
        R[5] = R[5] * sc + p * c1.y;
        R[6] = R[6] * sc + p * c1.z;
        R[7] = R[7] * sc + p * c1.w;
        m = nm;
        ii = nx; have = hn;
        if (hn) { c0 = n0f; c1 = n1f; }
    }

    if (lane == 0) { mw_s[wid] = m; Sw_s[wid] = S; }
    #pragma unroll
    for (int j = 0; j < 4; j++) {
        Rall[wid][lane * 4 + j]       = R[j];
        Rall[wid][128 + lane * 4 + j] = R[4 + j];
    }
    __syncthreads();

    float r = 0.f;
    if (en > s) {
        float M = mw_s[0];
        #pragma unroll
        for (int w = 1; w < 8; w++) M = fmaxf(M, mw_s[w]);
        float Ss = 0.f, Rs = 0.f;
        #pragma unroll
        for (int w = 0; w < 8; w++) {
            const float f = __expf(mw_s[w] - M);
            Ss += f * Sw_s[w];
            Rs += f * Rall[w][t];
        }
        r = Rs / (Ss + 1e-16f);
    }

    const size_t xb = (size_t)g * XDIM;
    split_bf16(h_s[t], g_x_h[xb + t],          g_x_l[xb + t]);
    split_bf16(r,      g_x_h[xb + HIDDEN + t], g_x_l[xb + HIDDEN + t]);
}

// ---------------- shared MMA helpers ----------------
__device__ __forceinline__ void mma_bf16(float c[4], const uint32_t a[4], const uint32_t b[2]) {
    asm volatile(
        "mma.sync.aligned.m16n8k16.row.col.f32.bf16.bf16.f32 "
        "{%0,%1,%2,%3}, {%4,%5,%6,%7}, {%8,%9}, {%0,%1,%2,%3};\n"
        : "+f"(c[0]), "+f"(c[1]), "+f"(c[2]), "+f"(c[3])
        : "r"(a[0]), "r"(a[1]), "r"(a[2]), "r"(a[3]), "r"(b[0]), "r"(b[1]));
}
__device__ __forceinline__ void cp16(__nv_bfloat16* dst, const __nv_bfloat16* src) {
    uint32_t d = (uint32_t)__cvta_generic_to_shared(dst);
    asm volatile("cp.async.cg.shared.global [%0], [%1], 16;\n" :: "r"(d), "l"(src));
}

// ======== gates GEMM, single wave: 128x128 tiles, 2 CTAs/SM, fused LSTM cell ========
#define GP 40
#define GSZ (128 * GP)
#define G_SMEM_BYTES (2 * 4 * GSZ * 2)   // 81920
#define GCP 132

__global__ void __launch_bounds__(256, 2)
k_gates(const __nv_bfloat16* __restrict__ A_h, const __nv_bfloat16* __restrict__ A_l,
        const __nv_bfloat16* __restrict__ B_h, const __nv_bfloat16* __restrict__ B_l,
        const float* __restrict__ bias) {
    extern __shared__ __nv_bfloat16 sg[];
    __shared__ float sbias[128];

    const int tid  = threadIdx.x;
    const int lane = tid & 31;
    const int wid  = tid >> 5;
    const int wm   = wid & 3;
    const int wn   = wid >> 2;
    const int g8   = lane >> 2;
    const int tg   = lane & 3;

    const int m0 = blockIdx.y * 128;
    const int n0 = blockIdx.x * 128;
    const int dbase = n0 >> 2;

    if (tid < 128) sbias[tid] = bias[n0 + tid];

    float acc[2][8][4];
    #pragma unroll
    for (int im = 0; im < 2; im++)
        #pragma unroll
        for (int in = 0; in < 8; in++)
            #pragma unroll
            for (int q = 0; q < 4; q++) acc[im][in][q] = 0.f;

    const int r0 = tid >> 2, q0 = tid & 3;
    const int r1 = (tid + 256) >> 2, q1 = tid & 3;

    auto stage = [&](int t) {
        const int stg = t & 1;
        const int kb = t * 32;
        __nv_bfloat16* base = sg + stg * 4 * GSZ;
        __nv_bfloat16* dAh = base;
        __nv_bfloat16* dAl = base + GSZ;
        __nv_bfloat16* dBh = base + 2 * GSZ;
        __nv_bfloat16* dBl = base + 3 * GSZ;
        cp16(dAh + r0 * GP + q0 * 8, A_h + (size_t)(m0 + r0) * XDIM + kb + q0 * 8);
        cp16(dAh + r1 * GP + q1 * 8, A_h + (size_t)(m0 + r1) * XDIM + kb + q1 * 8);
        cp16(dAl + r0 * GP + q0 * 8, A_l + (size_t)(m0 + r0) * XDIM + kb + q0 * 8);
        cp16(dAl + r1 * GP + q1 * 8, A_l + (size_t)(m0 + r1) * XDIM + kb + q1 * 8);
        cp16(dBh + r0 * GP + q0 * 8, B_h + (size_t)(n0 + r0) * XDIM + kb + q0 * 8);
        cp16(dBh + r1 * GP + q1 * 8, B_h + (size_t)(n0 + r1) * XDIM + kb + q1 * 8);
        cp16(dBl + r0 * GP + q0 * 8, B_l + (size_t)(n0 + r0) * XDIM + kb + q0 * 8);
        cp16(dBl + r1 * GP + q1 * 8, B_l + (size_t)(n0 + r1) * XDIM + kb + q1 * 8);
    };

    stage(0);
    asm volatile("cp.async.commit_group;\n");

    const int T = XDIM / 32;   // 16
    for (int t = 0; t < T; t++) {
        const int stg = t & 1;
        if (t + 1 < T) stage(t + 1);
        asm volatile("cp.async.commit_group;\n");
        asm volatile("cp.async.wait_group 1;\n");
        __syncthreads();

        const __nv_bfloat16* base = sg + stg * 4 * GSZ;
        const __nv_bfloat16* Ah = base;
        const __nv_bfloat16* Al = base + GSZ;
        const __nv_bfloat16* Bh = base + 2 * GSZ;
        const __nv_bfloat16* Bl = base + 3 * GSZ;

        #pragma unroll
        for (int kk = 0; kk < 32; kk += 16) {
            uint32_t ah[2][4], al[2][4];
            #pragma unroll
            for (int im = 0; im < 2; im++) {
                const int r = wm * 32 + im * 16 + g8;
                ah[im][0] = *reinterpret_cast<const uint32_t*>(Ah + r * GP + kk + 2 * tg);
                ah[im][1] = *reinterpret_cast<const uint32_t*>(Ah + (r + 8) * GP + kk + 2 * tg);
                ah[im][2] = *reinterpret_cast<const uint32_t*>(Ah + r * GP + kk + 2 * tg + 8);
                ah[im][3] = *reinterpret_cast<const uint32_t*>(Ah + (r + 8) * GP + kk + 2 * tg + 8);
                al[im][0] = *reinterpret_cast<const uint32_t*>(Al + r * GP + kk + 2 * tg);
                al[im][1] = *reinterpret_cast<const uint32_t*>(Al + (r + 8) * GP + kk + 2 * tg);
                al[im][2] = *reinterpret_cast<const uint32_t*>(Al + r * GP + kk + 2 * tg + 8);
                al[im][3] = *reinterpret_cast<const uint32_t*>(Al + (r + 8) * GP + kk + 2 * tg + 8);
            }
            #pragma unroll
            for (int in = 0; in < 8; in++) {
                const int rn = wn * 64 + in * 8 + g8;
                uint32_t bh[2], bl[2];
                bh[0] = *reinterpret_cast<const uint32_t*>(Bh + rn * GP + kk + 2 * tg);
                bh[1] = *reinterpret_cast<const uint32_t*>(Bh + rn * GP + kk + 2 * tg + 8);
                bl[0] = *reinterpret_cast<const uint32_t*>(Bl + rn * GP + kk + 2 * tg);
                bl[1] = *reinterpret_cast<const uint32_t*>(Bl + rn * GP + kk + 2 * tg + 8);
                #pragma unroll
                for (int im = 0; im < 2; im++) {
                    mma_bf16(acc[im][in], ah[im], bh);
                    mma_bf16(acc[im][in], ah[im], bl);
                    mma_bf16(acc[im][in], al[im], bh);
                }
            }
        }
        __syncthreads();
    }

    // ---- fused LSTM cell epilogue ----
    float* sC = reinterpret_cast<float*>(sg);
    #pragma unroll
    for (int im = 0; im < 2; im++)
        #pragma unroll
        for (int in = 0; in < 8; in++) {
            const int rl = wm * 32 + im * 16 + g8;
            const int cl = wn * 64 + in * 8 + 2 * tg;
            sC[rl * GCP + cl]           = acc[im][in][0] + sbias[cl];
            sC[rl * GCP + cl + 1]       = acc[im][in][1] + sbias[cl + 1];
            sC[(rl + 8) * GCP + cl]     = acc[im][in][2] + sbias[cl];
            sC[(rl + 8) * GCP + cl + 1] = acc[im][in][3] + sbias[cl + 1];
        }
    __syncthreads();

    #pragma unroll
    for (int it = 0; it < 16; it++) {
        const int idx = tid + it * 256;
        const int row = idx >> 5, dl = idx & 31;
        const float4 gv = *reinterpret_cast<const float4*>(&sC[row * GCP + dl * 4]); // i,f,g,o
        const int gi = m0 + row;
        const int d  = dbase + dl;
        const size_t hb = (size_t)gi * HIDDEN + d;
        const float c_old = g_c[hb];
        const float c_new = sigf(gv.y) * c_old + sigf(gv.x) * tanhf(gv.z);
        const float h_new = sigf(gv.w) * tanhf(c_new);
        g_c[hb] = c_new;
        g_h[hb] = h_new;
        split_bf16(h_new, g_x_h[(size_t)gi * XDIM + d], g_x_l[(size_t)gi * XDIM + d]);
    }
}

// ---------------- generic GEMM for the two MLP launches ----------------
#define BM 64
#define BN 128
#define BK 32
#define PITCH 40
#define SZ_A (64 * PITCH)
#define SZ_B (128 * PITCH)
#define SMEM_HALFS (2 * SZ_A * 2 + 2 * SZ_B * 2)
#define SMEM_BYTES (SMEM_HALFS * 2)

__global__ void __launch_bounds__(256, 3)
k_gemm(const __nv_bfloat16* __restrict__ A_h, const __nv_bfloat16* __restrict__ A_l,
       const __nv_bfloat16* __restrict__ B_h, const __nv_bfloat16* __restrict__ B_l,
       const float* __restrict__ bias,
       float* __restrict__ C, __nv_bfloat16* __restrict__ C_h, __nv_bfloat16* __restrict__ C_l,
       int N, int K, int mode) {
    extern __shared__ __nv_bfloat16 sm[];
    __nv_bfloat16* sA_h = sm;
    __nv_bfloat16* sA_l = sA_h + 2 * SZ_A;
    __nv_bfloat16* sB_h = sA_l + 2 * SZ_A;
    __nv_bfloat16* sB_l = sB_h + 2 * SZ_B;

    const int tid  = threadIdx.x;
    const int lane = tid & 31;
    const int wid  = tid >> 5;
    const int wm   = wid & 1;
    const int wn   = wid >> 1;
    const int g8   = lane >> 2;
    const int tg   = lane & 3;

    const int m0 = blockIdx.y * BM;
    const int n0 = blockIdx.x * BN;
    const int T  = K / BK;

    const int ar = tid >> 2, aq = tid & 3;
    const int br0 = tid >> 2, br1 = (tid + 256) >> 2;

    float acc[2][4][4];
    #pragma unroll
    for (int im = 0; im < 2; im++)
        #pragma unroll
        for (int in = 0; in < 4; in++)
            #pragma unroll
            for (int q = 0; q < 4; q++) acc[im][in][q] = 0.f;

    auto stage = [&](int tile, int stg) {
        const int kb = tile * BK;
        __nv_bfloat16* dAh = sA_h + stg * SZ_A;
        __nv_bfloat16* dAl = sA_l + stg * SZ_A;
        __nv_bfloat16* dBh = sB_h + stg * SZ_B;
        __nv_bfloat16* dBl = sB_l + stg * SZ_B;
        cp16(dAh + ar * PITCH + aq * 8, A_h + (size_t)(m0 + ar) * K + kb + aq * 8);
        cp16(dAl + ar * PITCH + aq * 8, A_l + (size_t)(m0 + ar) * K + kb + aq * 8);
        cp16(dBh + br0 * PITCH + aq * 8, B_h + (size_t)(n0 + br0) * K + kb + aq * 8);
        cp16(dBh + br1 * PITCH + aq * 8, B_h + (size_t)(n0 + br1) * K + kb + aq * 8);
        cp16(dBl + br0 * PITCH + aq * 8, B_l + (size_t)(n0 + br0) * K + kb + aq * 8);
        cp16(dBl + br1 * PITCH + aq * 8, B_l + (size_t)(n0 + br1) * K + kb + aq * 8);
    };

    stage(0, 0);
    asm volatile("cp.async.commit_group;\n");

    for (int t = 0; t < T; t++) {
        const int stg = t & 1;
        if (t + 1 < T) stage(t + 1, (t + 1) & 1);
        asm volatile("cp.async.commit_group;\n");
        asm volatile("cp.async.wait_group 1;\n");
        __syncthreads();

        const __nv_bfloat16* Ah = sA_h + stg * SZ_A;
        const __nv_bfloat16* Al = sA_l + stg * SZ_A;
        const __nv_bfloat16* Bh = sB_h + stg * SZ_B;
        const __nv_bfloat16* Bl = sB_l + stg * SZ_B;

        #pragma unroll
        for (int kk = 0; kk < BK; kk += 16) {
            uint32_t ah[2][4], al[2][4], bh[4][2], bl[4][2];
            #pragma unroll
            for (int im = 0; im < 2; im++) {
                const int r = wm * 32 + im * 16 + g8;
                ah[im][0] = *reinterpret_cast<const uint32_t*>(Ah + r * PITCH + kk + 2 * tg);
                ah[im][1] = *reinterpret_cast<const uint32_t*>(Ah + (r + 8) * PITCH + kk + 2 * tg);
                ah[im][2] = *reinterpret_cast<const uint32_t*>(Ah + r * PITCH + kk + 2 * tg + 8);
                ah[im][3] = *reinterpret_cast<const uint32_t*>(Ah + (r + 8) * PITCH + kk + 2 * tg + 8);
                al[im][0] = *reinterpret_cast<const uint32_t*>(Al + r * PITCH + kk + 2 * tg);
                al[im][1] = *reinterpret_cast<const uint32_t*>(Al + (r + 8) * PITCH + kk + 2 * tg);
                al[im][2] = *reinterpret_cast<const uint32_t*>(Al + r * PITCH + kk + 2 * tg + 8);
                al[im][3] = *reinterpret_cast<const uint32_t*>(Al + (r + 8) * PITCH + kk + 2 * tg + 8);
            }
            #pragma unroll
            for (int in = 0; in < 4; in++) {
                const int rn = wn * 32 + in * 8 + g8;
                bh[in][0] = *reinterpret_cast<const uint32_t*>(Bh + rn * PITCH + kk + 2 * tg);
                bh[in][1] = *reinterpret_cast<const uint32_t*>(Bh + rn * PITCH + kk + 2 * tg + 8);
                bl[in][0] = *reinterpret_cast<const uint32_t*>(Bl + rn * PITCH + kk + 2 * tg);
                bl[in][1] = *reinterpret_cast<const uint32_t*>(Bl + rn * PITCH + kk + 2 * tg + 8);
            }
            #pragma unroll
            for (int im = 0; im < 2; im++)
                #pragma unroll
                for (int in = 0; in < 4; in++) {
                    mma_bf16(acc[im][in], ah[im], bh[in]);
                    mma_bf16(acc[im][in], ah[im], bl[in]);
                    mma_bf16(acc[im][in], al[im], bh[in]);
                }
        }
        __syncthreads();
    }

    #pragma unroll
    for (int im = 0; im < 2; im++) {
        #pragma unroll
        for (int in = 0; in < 4; in++) {
            const int row0 = m0 + wm * 32 + im * 16 + g8;
            const int col  = n0 + wn * 32 + in * 8 + 2 * tg;
            const float b0 = bias[col], b1 = bias[col + 1];
            float v0 = acc[im][in][0] + b0;
            float v1 = acc[im][in][1] + b1;
            float v2 = acc[im][in][2] + b0;
            float v3 = acc[im][in][3] + b1;
            if (mode == 1) {
                v0 = fmaxf(v0, 0.f); v1 = fmaxf(v1, 0.f);
                v2 = fmaxf(v2, 0.f); v3 = fmaxf(v3, 0.f);
                __nv_bfloat16 h0, l0, h1, l1;
                split_bf16(v0, h0, l0); split_bf16(v1, h1, l1);
                *reinterpret_cast<__nv_bfloat162*>(&C_h[(size_t)row0 * N + col]) = __nv_bfloat162(h0, h1);
                *reinterpret_cast<__nv_bfloat162*>(&C_l[(size_t)row0 * N + col]) = __nv_bfloat162(l0, l1);
                split_bf16(v2, h0, l0); split_bf16(v3, h1, l1);
                *reinterpret_cast<__nv_bfloat162*>(&C_h[(size_t)(row0 + 8) * N + col]) = __nv_bfloat162(h0, h1);
                *reinterpret_cast<__nv_bfloat162*>(&C_l[(size_t)(row0 + 8) * N + col]) = __nv_bfloat162(l0, l1);
            } else {
                *reinterpret_cast<float2*>(&C[(size_t)row0 * N + col])       = make_float2(v0, v1);
                *reinterpret_cast<float2*>(&C[(size_t)(row0 + 8) * N + col]) = make_float2(v2, v3);
            }
        }
    }
}

// ---------------- launch ----------------
extern "C" void kernel_launch(void* const* d_in, const int* in_sizes, int n_in,
                              void* d_out, int out_size) {
    const float* emb  = (const float*)d_in[0];
    const int*   bidx = (const int*)d_in[1];
    const float* W_ih = (const float*)d_in[2];
    const float* W_hh = (const float*)d_in[3];
    const float* b_ih = (const float*)d_in[4];
    const float* b_hh = (const float*)d_in[5];
    const float* W1   = (const float*)d_in[6];
    const float* b1   = (const float*)d_in[7];
    const float* W2   = (const float*)d_in[8];
    const float* b2   = (const float*)d_in[9];
    float* out = (float*)d_out;
    const int nn = in_sizes[1];

    float *p_bc;
    __nv_bfloat16 *p_x_h, *p_x_l, *p_hdn_h, *p_hdn_l;
    __nv_bfloat16 *p_Wc_h, *p_Wc_l, *p_W1_h, *p_W1_l, *p_W2_h, *p_W2_l;
    cudaGetSymbolAddress((void**)&p_bc,    g_bc);
    cudaGetSymbolAddress((void**)&p_x_h,   g_x_h);
    cudaGetSymbolAddress((void**)&p_x_l,   g_x_l);
    cudaGetSymbolAddress((void**)&p_hdn_h, g_hdn_h);
    cudaGetSymbolAddress((void**)&p_hdn_l, g_hdn_l);
    cudaGetSymbolAddress((void**)&p_Wc_h,  g_Wc_h);
    cudaGetSymbolAddress((void**)&p_Wc_l,  g_Wc_l);
    cudaGetSymbolAddress((void**)&p_W1_h,  g_W1_h);
    cudaGetSymbolAddress((void**)&p_W1_l,  g_W1_l);
    cudaGetSymbolAddress((void**)&p_W2_h,  g_W2_h);
    cudaGetSymbolAddress((void**)&p_W2_l,  g_W2_l);

    cudaFuncSetAttribute(k_gemm,  cudaFuncAttributeMaxDynamicSharedMemorySize, SMEM_BYTES);
    cudaFuncSetAttribute(k_gates, cudaFuncAttributeMaxDynamicSharedMemorySize, G_SMEM_BYTES);

    k_setup<<<2048, 256>>>(bidx, nn, W_ih, W_hh, b_ih, b_hh, W1, W2);

    for (int s = 0; s < STEPS; s++) {
        k_attention<<<N_GRAPHS, 256>>>(emb);
        k_gates<<<dim3(GATESD / 128, N_GRAPHS / 128), 256, G_SMEM_BYTES>>>(
            p_x_h, p_x_l, p_Wc_h, p_Wc_l, p_bc);
    }

    // MLP readout
    k_gemm<<<dim3(HIDDEN / BN, N_GRAPHS / BM), 256, SMEM_BYTES>>>(
        p_x_h, p_x_l, p_W1_h, p_W1_l, b1, nullptr, p_hdn_h, p_hdn_l,
        HIDDEN, XDIM, 1);
    k_gemm<<<dim3(HIDDEN / BN, N_GRAPHS / BM), 256, SMEM_BYTES>>>(
        p_hdn_h, p_hdn_l, p_W2_h, p_W2_l, b2, out, nullptr, nullptr,
        HIDDEN, HIDDEN, 0);
}

// round 15
// speedup vs baseline: 1.6119x; 1.6119x over previous
#include <cuda_runtime.h>
#include <cuda_bf16.h>
#include <cstdint>
#include <math_constants.h>

#define N_GRAPHS 4096
#define HIDDEN   256
#define STEPS    6
#define GATESD   1024   // 4*HIDDEN
#define XDIM     512    // 2*HIDDEN

// ---------------- scratch (no allocation allowed) ----------------
__device__ float g_h[N_GRAPHS * HIDDEN];
__device__ float g_c[N_GRAPHS * HIDDEN];
__device__ float g_bc[GATESD];                 // b_ih + b_hh, gate-interleaved
__device__ int   g_start[N_GRAPHS];
__device__ int   g_end[N_GRAPHS];
__device__ __nv_bfloat16 g_x_h[N_GRAPHS * XDIM],     g_x_l[N_GRAPHS * XDIM];
__device__ __nv_bfloat16 g_hdn_h[N_GRAPHS * HIDDEN], g_hdn_l[N_GRAPHS * HIDDEN];
__device__ __nv_bfloat16 g_Wc_h[GATESD * XDIM],      g_Wc_l[GATESD * XDIM];   // gate-interleaved rows
__device__ __nv_bfloat16 g_W1_h[HIDDEN * XDIM],      g_W1_l[HIDDEN * XDIM];
__device__ __nv_bfloat16 g_W2_h[HIDDEN * HIDDEN],    g_W2_l[HIDDEN * HIDDEN];

__device__ __forceinline__ void split_bf16(float v, __nv_bfloat16& h, __nv_bfloat16& l) {
    h = __float2bfloat16(v);
    l = __float2bfloat16(v - __bfloat162float(h));
}
__device__ __forceinline__ float sigf(float x) { return 1.f / (1.f + expf(-x)); }

// ---------------- fused setup: init h/c, segments, weight fold+split ----------------
__global__ void k_setup(const int* __restrict__ idx, int nn,
                        const float* __restrict__ W_ih, const float* __restrict__ W_hh,
                        const float* __restrict__ b_ih, const float* __restrict__ b_hh,
                        const float* __restrict__ W1, const float* __restrict__ W2) {
    const int i = blockIdx.x * blockDim.x + threadIdx.x;   // 524288 threads

    g_h[i] = 0.f;              g_h[i + 524288] = 0.f;
    g_c[i] = 0.f;              g_c[i + 524288] = 0.f;
    if (i < N_GRAPHS) { g_start[i] = 0; g_end[i] = 0; }
    __threadfence();

    if (i < nn) {
        const int g = idx[i];
        if ((unsigned)g < (unsigned)N_GRAPHS) {
            if (i == 0      || idx[i - 1] != g) g_start[g] = i;
            if (i == nn - 1 || idx[i + 1] != g) g_end[g]   = i + 1;
        }
    }

    {
        const int np = i >> 9;
        const int k  = i & 511;
        const int d = np >> 2, gate = np & 3;
        const int orig = gate * HIDDEN + d;
        float v = W_ih[orig * XDIM + k];
        if (k < HIDDEN) v += W_hh[orig * HIDDEN + k];
        split_bf16(v, g_Wc_h[i], g_Wc_l[i]);
    }
    if (i < GATESD) {
        const int d2 = i >> 2, g2 = i & 3;
        const int o2 = g2 * HIDDEN + d2;
        g_bc[i] = b_ih[o2] + b_hh[o2];
    }
    if (i < HIDDEN * XDIM)   split_bf16(W1[i], g_W1_h[i], g_W1_l[i]);
    if (i < HIDDEN * HIDDEN) split_bf16(W2[i], g_W2_h[i], g_W2_l[i]);
}

// ---------------- single-pass attention, depth-1 prefetch, 5 CTAs/SM ----------------
__global__ void __launch_bounds__(256, 5)
k_attention(const float* __restrict__ emb) {
    const int g    = blockIdx.x;
    const int t    = threadIdx.x;
    const int lane = t & 31;
    const int wid  = t >> 5;

    __shared__ float h_s[HIDDEN];
    __shared__ float Rall[8][HIDDEN];
    __shared__ float mw_s[8], Sw_s[8];

    h_s[t] = g_h[(size_t)g * HIDDEN + t];
    const int s  = g_start[g];
    const int en = g_end[g];
    __syncthreads();

    const float4* h4 = reinterpret_cast<const float4*>(h_s);
    const float4 hv0 = h4[lane];
    const float4 hv1 = h4[lane + 32];

    float m = -CUDART_INF_F, S = 0.f;
    float R[8] = {0.f, 0.f, 0.f, 0.f, 0.f, 0.f, 0.f, 0.f};

    int ii = s + wid;
    float4 c0, c1;
    bool have = (ii < en);
    if (have) {
        const float4* r4 = reinterpret_cast<const float4*>(emb + (size_t)ii * HIDDEN);
        c0 = r4[lane]; c1 = r4[lane + 32];
    }
    while (have) {
        const int nx = ii + 8;
        const bool hn = nx < en;
        float4 n0f, n1f;
        if (hn) {
            const float4* r4 = reinterpret_cast<const float4*>(emb + (size_t)nx * HIDDEN);
            n0f = r4[lane]; n1f = r4[lane + 32];
        }
        float d = c0.x * hv0.x + c0.y * hv0.y + c0.z * hv0.z + c0.w * hv0.w
                + c1.x * hv1.x + c1.y * hv1.y + c1.z * hv1.z + c1.w * hv1.w;
        #pragma unroll
        for (int o = 16; o > 0; o >>= 1) d += __shfl_xor_sync(0xffffffffu, d, o);
        const float nm = fmaxf(m, d);
        const float sc = __expf(m - nm);
        const float p  = __expf(d - nm);
        S = S * sc + p;
        R[0] = R[0] * sc + p * c0.x;
        R[1] = R[1] * sc + p * c0.y;
        R[2] = R[2] * sc + p * c0.z;
        R[3] = R[3] * sc + p * c0.w;
        R[4] = R[4] * sc + p * c1.x;
        R[5] = R[5] * sc + p * c1.y;
        R[6] = R[6] * sc + p * c1.z;
        R[7] = R[7] * sc + p * c1.w;
        m = nm;
        ii = nx; have = hn;
        if (hn) { c0 = n0f; c1 = n1f; }
    }

    if (lane == 0) { mw_s[wid] = m; Sw_s[wid] = S; }
    #pragma unroll
    for (int j = 0; j < 4; j++) {
        Rall[wid][lane * 4 + j]       = R[j];
        Rall[wid][128 + lane * 4 + j] = R[4 + j];
    }
    __syncthreads();

    float r = 0.f;
    if (en > s) {
        float M = mw_s[0];
        #pragma unroll
        for (int w = 1; w < 8; w++) M = fmaxf(M, mw_s[w]);
        float Ss = 0.f, Rs = 0.f;
        #pragma unroll
        for (int w = 0; w < 8; w++) {
            const float f = __expf(mw_s[w] - M);
            Ss += f * Sw_s[w];
            Rs += f * Rall[w][t];
        }
        r = Rs / (Ss + 1e-16f);
    }

    const size_t xb = (size_t)g * XDIM;
    split_bf16(h_s[t], g_x_h[xb + t],          g_x_l[xb + t]);
    split_bf16(r,      g_x_h[xb + HIDDEN + t], g_x_l[xb + HIDDEN + t]);
}

// ---------------- shared MMA helpers ----------------
__device__ __forceinline__ void mma_bf16(float c[4], const uint32_t a[4], const uint32_t b[2]) {
    asm volatile(
        "mma.sync.aligned.m16n8k16.row.col.f32.bf16.bf16.f32 "
        "{%0,%1,%2,%3}, {%4,%5,%6,%7}, {%8,%9}, {%0,%1,%2,%3};\n"
        : "+f"(c[0]), "+f"(c[1]), "+f"(c[2]), "+f"(c[3])
        : "r"(a[0]), "r"(a[1]), "r"(a[2]), "r"(a[3]), "r"(b[0]), "r"(b[1]));
}
__device__ __forceinline__ void cp16(__nv_bfloat16* dst, const __nv_bfloat16* src) {
    uint32_t d = (uint32_t)__cvta_generic_to_shared(dst);
    asm volatile("cp.async.cg.shared.global [%0], [%1], 16;\n" :: "r"(d), "l"(src));
}

// ======== gates GEMM, single wave: 128x128 tiles, 2 CTAs/SM, fused LSTM cell ========
#define GP 40
#define GSZ (128 * GP)
#define G_SMEM_BYTES (2 * 4 * GSZ * 2)   // 81920
#define GCP 132

__global__ void __launch_bounds__(256, 2)
k_gates(const __nv_bfloat16* __restrict__ A_h, const __nv_bfloat16* __restrict__ A_l,
        const __nv_bfloat16* __restrict__ B_h, const __nv_bfloat16* __restrict__ B_l,
        const float* __restrict__ bias) {
    extern __shared__ __nv_bfloat16 sg[];
    __shared__ float sbias[128];

    const int tid  = threadIdx.x;
    const int lane = tid & 31;
    const int wid  = tid >> 5;
    const int wm   = wid & 3;
    const int wn   = wid >> 2;
    const int g8   = lane >> 2;
    const int tg   = lane & 3;

    const int m0 = blockIdx.y * 128;
    const int n0 = blockIdx.x * 128;
    const int dbase = n0 >> 2;

    if (tid < 128) sbias[tid] = bias[n0 + tid];

    float acc[2][8][4];
    #pragma unroll
    for (int im = 0; im < 2; im++)
        #pragma unroll
        for (int in = 0; in < 8; in++)
            #pragma unroll
            for (int q = 0; q < 4; q++) acc[im][in][q] = 0.f;

    const int r0 = tid >> 2, q0 = tid & 3;
    const int r1 = (tid + 256) >> 2, q1 = tid & 3;

    auto stage = [&](int t) {
        const int stg = t & 1;
        const int kb = t * 32;
        __nv_bfloat16* base = sg + stg * 4 * GSZ;
        __nv_bfloat16* dAh = base;
        __nv_bfloat16* dAl = base + GSZ;
        __nv_bfloat16* dBh = base + 2 * GSZ;
        __nv_bfloat16* dBl = base + 3 * GSZ;
        cp16(dAh + r0 * GP + q0 * 8, A_h + (size_t)(m0 + r0) * XDIM + kb + q0 * 8);
        cp16(dAh + r1 * GP + q1 * 8, A_h + (size_t)(m0 + r1) * XDIM + kb + q1 * 8);
        cp16(dAl + r0 * GP + q0 * 8, A_l + (size_t)(m0 + r0) * XDIM + kb + q0 * 8);
        cp16(dAl + r1 * GP + q1 * 8, A_l + (size_t)(m0 + r1) * XDIM + kb + q1 * 8);
        cp16(dBh + r0 * GP + q0 * 8, B_h + (size_t)(n0 + r0) * XDIM + kb + q0 * 8);
        cp16(dBh + r1 * GP + q1 * 8, B_h + (size_t)(n0 + r1) * XDIM + kb + q1 * 8);
        cp16(dBl + r0 * GP + q0 * 8, B_l + (size_t)(n0 + r0) * XDIM + kb + q0 * 8);
        cp16(dBl + r1 * GP + q1 * 8, B_l + (size_t)(n0 + r1) * XDIM + kb + q1 * 8);
    };

    stage(0);
    asm volatile("cp.async.commit_group;\n");

    const int T = XDIM / 32;   // 16
    for (int t = 0; t < T; t++) {
        const int stg = t & 1;
        if (t + 1 < T) stage(t + 1);
        asm volatile("cp.async.commit_group;\n");
        asm volatile("cp.async.wait_group 1;\n");
        __syncthreads();

        const __nv_bfloat16* base = sg + stg * 4 * GSZ;
        const __nv_bfloat16* Ah = base;
        const __nv_bfloat16* Al = base + GSZ;
        const __nv_bfloat16* Bh = base + 2 * GSZ;
        const __nv_bfloat16* Bl = base + 3 * GSZ;

        #pragma unroll
        for (int kk = 0; kk < 32; kk += 16) {
            uint32_t ah[2][4], al[2][4];
            #pragma unroll
            for (int im = 0; im < 2; im++) {
                const int r = wm * 32 + im * 16 + g8;
                ah[im][0] = *reinterpret_cast<const uint32_t*>(Ah + r * GP + kk + 2 * tg);
                ah[im][1] = *reinterpret_cast<const uint32_t*>(Ah + (r + 8) * GP + kk + 2 * tg);
                ah[im][2] = *reinterpret_cast<const uint32_t*>(Ah + r * GP + kk + 2 * tg + 8);
                ah[im][3] = *reinterpret_cast<const uint32_t*>(Ah + (r + 8) * GP + kk + 2 * tg + 8);
                al[im][0] = *reinterpret_cast<const uint32_t*>(Al + r * GP + kk + 2 * tg);
                al[im][1] = *reinterpret_cast<const uint32_t*>(Al + (r + 8) * GP + kk + 2 * tg);
                al[im][2] = *reinterpret_cast<const uint32_t*>(Al + r * GP + kk + 2 * tg + 8);
                al[im][3] = *reinterpret_cast<const uint32_t*>(Al + (r + 8) * GP + kk + 2 * tg + 8);
            }
            #pragma unroll
            for (int in = 0; in < 8; in++) {
                const int rn = wn * 64 + in * 8 + g8;
                uint32_t bh[2], bl[2];
                bh[0] = *reinterpret_cast<const uint32_t*>(Bh + rn * GP + kk + 2 * tg);
                bh[1] = *reinterpret_cast<const uint32_t*>(Bh + rn * GP + kk + 2 * tg + 8);
                bl[0] = *reinterpret_cast<const uint32_t*>(Bl + rn * GP + kk + 2 * tg);
                bl[1] = *reinterpret_cast<const uint32_t*>(Bl + rn * GP + kk + 2 * tg + 8);
                #pragma unroll
                for (int im = 0; im < 2; im++) {
                    mma_bf16(acc[im][in], ah[im], bh);
                    mma_bf16(acc[im][in], ah[im], bl);
                    mma_bf16(acc[im][in], al[im], bh);
                }
            }
        }
        __syncthreads();
    }

    // ---- fused LSTM cell epilogue ----
    float* sC = reinterpret_cast<float*>(sg);
    #pragma unroll
    for (int im = 0; im < 2; im++)
        #pragma unroll
        for (int in = 0; in < 8; in++) {
            const int rl = wm * 32 + im * 16 + g8;
            const int cl = wn * 64 + in * 8 + 2 * tg;
            sC[rl * GCP + cl]           = acc[im][in][0] + sbias[cl];
            sC[rl * GCP + cl + 1]       = acc[im][in][1] + sbias[cl + 1];
            sC[(rl + 8) * GCP + cl]     = acc[im][in][2] + sbias[cl];
            sC[(rl + 8) * GCP + cl + 1] = acc[im][in][3] + sbias[cl + 1];
        }
    __syncthreads();

    #pragma unroll
    for (int it = 0; it < 16; it++) {
        const int idx = tid + it * 256;
        const int row = idx >> 5, dl = idx & 31;
        const float4 gv = *reinterpret_cast<const float4*>(&sC[row * GCP + dl * 4]); // i,f,g,o
        const int gi = m0 + row;
        const int d  = dbase + dl;
        const size_t hb = (size_t)gi * HIDDEN + d;
        const float c_old = g_c[hb];
        const float c_new = sigf(gv.y) * c_old + sigf(gv.x) * tanhf(gv.z);
        const float h_new = sigf(gv.w) * tanhf(c_new);
        g_c[hb] = c_new;
        g_h[hb] = h_new;
        split_bf16(h_new, g_x_h[(size_t)gi * XDIM + d], g_x_l[(size_t)gi * XDIM + d]);
    }
}

// ---------------- generic GEMM for the two MLP launches ----------------
#define BM 64
#define BN 128
#define BK 32
#define PITCH 40
#define SZ_A (64 * PITCH)
#define SZ_B (128 * PITCH)
#define SMEM_HALFS (2 * SZ_A * 2 + 2 * SZ_B * 2)
#define SMEM_BYTES (SMEM_HALFS * 2)

__global__ void __launch_bounds__(256, 3)
k_gemm(const __nv_bfloat16* __restrict__ A_h, const __nv_bfloat16* __restrict__ A_l,
       const __nv_bfloat16* __restrict__ B_h, const __nv_bfloat16* __restrict__ B_l,
       const float* __restrict__ bias,
       float* __restrict__ C, __nv_bfloat16* __restrict__ C_h, __nv_bfloat16* __restrict__ C_l,
       int N, int K, int mode) {
    extern __shared__ __nv_bfloat16 sm[];
    __nv_bfloat16* sA_h = sm;
    __nv_bfloat16* sA_l = sA_h + 2 * SZ_A;
    __nv_bfloat16* sB_h = sA_l + 2 * SZ_A;
    __nv_bfloat16* sB_l = sB_h + 2 * SZ_B;

    const int tid  = threadIdx.x;
    const int lane = tid & 31;
    const int wid  = tid >> 5;
    const int wm   = wid & 1;
    const int wn   = wid >> 1;
    const int g8   = lane >> 2;
    const int tg   = lane & 3;

    const int m0 = blockIdx.y * BM;
    const int n0 = blockIdx.x * BN;
    const int T  = K / BK;

    const int ar = tid >> 2, aq = tid & 3;
    const int br0 = tid >> 2, br1 = (tid + 256) >> 2;

    float acc[2][4][4];
    #pragma unroll
    for (int im = 0; im < 2; im++)
        #pragma unroll
        for (int in = 0; in < 4; in++)
            #pragma unroll
            for (int q = 0; q < 4; q++) acc[im][in][q] = 0.f;

    auto stage = [&](int tile, int stg) {
        const int kb = tile * BK;
        __nv_bfloat16* dAh = sA_h + stg * SZ_A;
        __nv_bfloat16* dAl = sA_l + stg * SZ_A;
        __nv_bfloat16* dBh = sB_h + stg * SZ_B;
        __nv_bfloat16* dBl = sB_l + stg * SZ_B;
        cp16(dAh + ar * PITCH + aq * 8, A_h + (size_t)(m0 + ar) * K + kb + aq * 8);
        cp16(dAl + ar * PITCH + aq * 8, A_l + (size_t)(m0 + ar) * K + kb + aq * 8);
        cp16(dBh + br0 * PITCH + aq * 8, B_h + (size_t)(n0 + br0) * K + kb + aq * 8);
        cp16(dBh + br1 * PITCH + aq * 8, B_h + (size_t)(n0 + br1) * K + kb + aq * 8);
        cp16(dBl + br0 * PITCH + aq * 8, B_l + (size_t)(n0 + br0) * K + kb + aq * 8);
        cp16(dBl + br1 * PITCH + aq * 8, B_l + (size_t)(n0 + br1) * K + kb + aq * 8);
    };

    stage(0, 0);
    asm volatile("cp.async.commit_group;\n");

    for (int t = 0; t < T; t++) {
        const int stg = t & 1;
        if (t + 1 < T) stage(t + 1, (t + 1) & 1);
        asm volatile("cp.async.commit_group;\n");
        asm volatile("cp.async.wait_group 1;\n");
        __syncthreads();

        const __nv_bfloat16* Ah = sA_h + stg * SZ_A;
        const __nv_bfloat16* Al = sA_l + stg * SZ_A;
        const __nv_bfloat16* Bh = sB_h + stg * SZ_B;
        const __nv_bfloat16* Bl = sB_l + stg * SZ_B;

        #pragma unroll
        for (int kk = 0; kk < BK; kk += 16) {
            uint32_t ah[2][4], al[2][4], bh[4][2], bl[4][2];
            #pragma unroll
            for (int im = 0; im < 2; im++) {
                const int r = wm * 32 + im * 16 + g8;
                ah[im][0] = *reinterpret_cast<const uint32_t*>(Ah + r * PITCH + kk + 2 * tg);
                ah[im][1] = *reinterpret_cast<const uint32_t*>(Ah + (r + 8) * PITCH + kk + 2 * tg);
                ah[im][2] = *reinterpret_cast<const uint32_t*>(Ah + r * PITCH + kk + 2 * tg + 8);
                ah[im][3] = *reinterpret_cast<const uint32_t*>(Ah + (r + 8) * PITCH + kk + 2 * tg + 8);
                al[im][0] = *reinterpret_cast<const uint32_t*>(Al + r * PITCH + kk + 2 * tg);
                al[im][1] = *reinterpret_cast<const uint32_t*>(Al + (r + 8) * PITCH + kk + 2 * tg);
                al[im][2] = *reinterpret_cast<const uint32_t*>(Al + r * PITCH + kk + 2 * tg + 8);
                al[im][3] = *reinterpret_cast<const uint32_t*>(Al + (r + 8) * PITCH + kk + 2 * tg + 8);
            }
            #pragma unroll
            for (int in = 0; in < 4; in++) {
                const int rn = wn * 32 + in * 8 + g8;
                bh[in][0] = *reinterpret_cast<const uint32_t*>(Bh + rn * PITCH + kk + 2 * tg);
                bh[in][1] = *reinterpret_cast<const uint32_t*>(Bh + rn * PITCH + kk + 2 * tg + 8);
                bl[in][0] = *reinterpret_cast<const uint32_t*>(Bl + rn * PITCH + kk + 2 * tg);
                bl[in][1] = *reinterpret_cast<const uint32_t*>(Bl + rn * PITCH + kk + 2 * tg + 8);
            }
            #pragma unroll
            for (int im = 0; im < 2; im++)
                #pragma unroll
                for (int in = 0; in < 4; in++) {
                    mma_bf16(acc[im][in], ah[im], bh[in]);
                    mma_bf16(acc[im][in], ah[im], bl[in]);
                    mma_bf16(acc[im][in], al[im], bh[in]);
                }
        }
        __syncthreads();
    }

    #pragma unroll
    for (int im = 0; im < 2; im++) {
        #pragma unroll
        for (int in = 0; in < 4; in++) {
            const int row0 = m0 + wm * 32 + im * 16 + g8;
            const int col  = n0 + wn * 32 + in * 8 + 2 * tg;
            const float b0 = bias[col], b1 = bias[col + 1];
            float v0 = acc[im][in][0] + b0;
            float v1 = acc[im][in][1] + b1;
            float v2 = acc[im][in][2] + b0;
            float v3 = acc[im][in][3] + b1;
            if (mode == 1) {
                v0 = fmaxf(v0, 0.f); v1 = fmaxf(v1, 0.f);
                v2 = fmaxf(v2, 0.f); v3 = fmaxf(v3, 0.f);
                __nv_bfloat16 h0, l0, h1, l1;
                split_bf16(v0, h0, l0); split_bf16(v1, h1, l1);
                *reinterpret_cast<__nv_bfloat162*>(&C_h[(size_t)row0 * N + col]) = __nv_bfloat162(h0, h1);
                *reinterpret_cast<__nv_bfloat162*>(&C_l[(size_t)row0 * N + col]) = __nv_bfloat162(l0, l1);
                split_bf16(v2, h0, l0); split_bf16(v3, h1, l1);
                *reinterpret_cast<__nv_bfloat162*>(&C_h[(size_t)(row0 + 8) * N + col]) = __nv_bfloat162(h0, h1);
                *reinterpret_cast<__nv_bfloat162*>(&C_l[(size_t)(row0 + 8) * N + col]) = __nv_bfloat162(l0, l1);
            } else {
                *reinterpret_cast<float2*>(&C[(size_t)row0 * N + col])       = make_float2(v0, v1);
                *reinterpret_cast<float2*>(&C[(size_t)(row0 + 8) * N + col]) = make_float2(v2, v3);
            }
        }
    }
}

// ---------------- launch ----------------
extern "C" void kernel_launch(void* const* d_in, const int* in_sizes, int n_in,
                              void* d_out, int out_size) {
    const float* emb  = (const float*)d_in[0];
    const int*   bidx = (const int*)d_in[1];
    const float* W_ih = (const float*)d_in[2];
    const float* W_hh = (const float*)d_in[3];
    const float* b_ih = (const float*)d_in[4];
    const float* b_hh = (const float*)d_in[5];
    const float* W1   = (const float*)d_in[6];
    const float* b1   = (const float*)d_in[7];
    const float* W2   = (const float*)d_in[8];
    const float* b2   = (const float*)d_in[9];
    float* out = (float*)d_out;
    const int nn = in_sizes[1];

    float *p_bc;
    __nv_bfloat16 *p_x_h, *p_x_l, *p_hdn_h, *p_hdn_l;
    __nv_bfloat16 *p_Wc_h, *p_Wc_l, *p_W1_h, *p_W1_l, *p_W2_h, *p_W2_l;
    cudaGetSymbolAddress((void**)&p_bc,    g_bc);
    cudaGetSymbolAddress((void**)&p_x_h,   g_x_h);
    cudaGetSymbolAddress((void**)&p_x_l,   g_x_l);
    cudaGetSymbolAddress((void**)&p_hdn_h, g_hdn_h);
    cudaGetSymbolAddress((void**)&p_hdn_l, g_hdn_l);
    cudaGetSymbolAddress((void**)&p_Wc_h,  g_Wc_h);
    cudaGetSymbolAddress((void**)&p_Wc_l,  g_Wc_l);
    cudaGetSymbolAddress((void**)&p_W1_h,  g_W1_h);
    cudaGetSymbolAddress((void**)&p_W1_l,  g_W1_l);
    cudaGetSymbolAddress((void**)&p_W2_h,  g_W2_h);
    cudaGetSymbolAddress((void**)&p_W2_l,  g_W2_l);

    cudaFuncSetAttribute(k_gemm,  cudaFuncAttributeMaxDynamicSharedMemorySize, SMEM_BYTES);
    cudaFuncSetAttribute(k_gates, cudaFuncAttributeMaxDynamicSharedMemorySize, G_SMEM_BYTES);

    k_setup<<<2048, 256>>>(bidx, nn, W_ih, W_hh, b_ih, b_hh, W1, W2);

    for (int s = 0; s < STEPS; s++) {
        k_attention<<<N_GRAPHS, 256>>>(emb);
        k_gates<<<dim3(GATESD / 128, N_GRAPHS / 128), 256, G_SMEM_BYTES>>>(
            p_x_h, p_x_l, p_Wc_h, p_Wc_l, p_bc);
    }

    // MLP readout
    k_gemm<<<dim3(HIDDEN / BN, N_GRAPHS / BM), 256, SMEM_BYTES>>>(
        p_x_h, p_x_l, p_W1_h, p_W1_l, b1, nullptr, p_hdn_h, p_hdn_l,
        HIDDEN, XDIM, 1);
    k_gemm<<<dim3(HIDDEN / BN, N_GRAPHS / BM), 256, SMEM_BYTES>>>(
        p_hdn_h, p_hdn_l, p_W2_h, p_W2_l, b2, out, nullptr, nullptr,
        HIDDEN, HIDDEN, 0);
}

// round 16
// speedup vs baseline: 1.6276x; 1.0097x over previous
#include <cuda_runtime.h>
#include <cuda_bf16.h>
#include <cstdint>
#include <math_constants.h>

#define N_GRAPHS 4096
#define HIDDEN   256
#define STEPS    6
#define GATESD   1024   // 4*HIDDEN
#define XDIM     512    // 2*HIDDEN

// ---------------- scratch (no allocation allowed) ----------------
__device__ float g_h[N_GRAPHS * HIDDEN];
__device__ float g_c[N_GRAPHS * HIDDEN];
__device__ float g_bc[GATESD];                 // b_ih + b_hh, gate-interleaved
__device__ int   g_start[N_GRAPHS];
__device__ int   g_end[N_GRAPHS];
__device__ __nv_bfloat16 g_x_h[N_GRAPHS * XDIM],     g_x_l[N_GRAPHS * XDIM];
__device__ __nv_bfloat16 g_hdn_h[N_GRAPHS * HIDDEN], g_hdn_l[N_GRAPHS * HIDDEN];
__device__ __nv_bfloat16 g_Wc_h[GATESD * XDIM],      g_Wc_l[GATESD * XDIM];   // gate-interleaved rows
__device__ __nv_bfloat16 g_W1_h[HIDDEN * XDIM],      g_W1_l[HIDDEN * XDIM];
__device__ __nv_bfloat16 g_W2_h[HIDDEN * HIDDEN],    g_W2_l[HIDDEN * HIDDEN];

__device__ __forceinline__ void split_bf16(float v, __nv_bfloat16& h, __nv_bfloat16& l) {
    h = __float2bfloat16(v);
    l = __float2bfloat16(v - __bfloat162float(h));
}
__device__ __forceinline__ float sigf(float x) { return 1.f / (1.f + expf(-x)); }

// ---------------- fused setup: init h/c, segments, weight fold+split ----------------
__global__ void k_setup(const int* __restrict__ idx, int nn,
                        const float* __restrict__ W_ih, const float* __restrict__ W_hh,
                        const float* __restrict__ b_ih, const float* __restrict__ b_hh,
                        const float* __restrict__ W1, const float* __restrict__ W2) {
    const int i = blockIdx.x * blockDim.x + threadIdx.x;   // 524288 threads

    g_h[i] = 0.f;              g_h[i + 524288] = 0.f;
    g_c[i] = 0.f;              g_c[i + 524288] = 0.f;
    if (i < N_GRAPHS) { g_start[i] = 0; g_end[i] = 0; }
    __threadfence();

    if (i < nn) {
        const int g = idx[i];
        if ((unsigned)g < (unsigned)N_GRAPHS) {
            if (i == 0      || idx[i - 1] != g) g_start[g] = i;
            if (i == nn - 1 || idx[i + 1] != g) g_end[g]   = i + 1;
        }
    }

    {
        const int np = i >> 9;
        const int k  = i & 511;
        const int d = np >> 2, gate = np & 3;
        const int orig = gate * HIDDEN + d;
        float v = W_ih[orig * XDIM + k];
        if (k < HIDDEN) v += W_hh[orig * HIDDEN + k];
        split_bf16(v, g_Wc_h[i], g_Wc_l[i]);
    }
    if (i < GATESD) {
        const int d2 = i >> 2, g2 = i & 3;
        const int o2 = g2 * HIDDEN + d2;
        g_bc[i] = b_ih[o2] + b_hh[o2];
    }
    if (i < HIDDEN * XDIM)   split_bf16(W1[i], g_W1_h[i], g_W1_l[i]);
    if (i < HIDDEN * HIDDEN) split_bf16(W2[i], g_W2_h[i], g_W2_l[i]);
}

// ---------------- single-pass attention, depth-1 prefetch, 5 CTAs/SM ----------------
__global__ void __launch_bounds__(256, 5)
k_attention(const float* __restrict__ emb) {
    const int g    = blockIdx.x;
    const int t    = threadIdx.x;
    const int lane = t & 31;
    const int wid  = t >> 5;

    __shared__ float h_s[HIDDEN];
    __shared__ float Rall[8][HIDDEN];
    __shared__ float mw_s[8], Sw_s[8];

    h_s[t] = g_h[(size_t)g * HIDDEN + t];
    const int s  = g_start[g];
    const int en = g_end[g];
    __syncthreads();

    const float4* h4 = reinterpret_cast<const float4*>(h_s);
    const float4 hv0 = h4[lane];
    const float4 hv1 = h4[lane + 32];

    float m = -CUDART_INF_F, S = 0.f;
    float R[8] = {0.f, 0.f, 0.f, 0.f, 0.f, 0.f, 0.f, 0.f};

    int ii = s + wid;
    float4 c0, c1;
    bool have = (ii < en);
    if (have) {
        const float4* r4 = reinterpret_cast<const float4*>(emb + (size_t)ii * HIDDEN);
        c0 = r4[lane]; c1 = r4[lane + 32];
    }
    while (have) {
        const int nx = ii + 8;
        const bool hn = nx < en;
        float4 n0f, n1f;
        if (hn) {
            const float4* r4 = reinterpret_cast<const float4*>(emb + (size_t)nx * HIDDEN);
            n0f = r4[lane]; n1f = r4[lane + 32];
        }
        float d = c0.x * hv0.x + c0.y * hv0.y + c0.z * hv0.z + c0.w * hv0.w
                + c1.x * hv1.x + c1.y * hv1.y + c1.z * hv1.z + c1.w * hv1.w;
        #pragma unroll
        for (int o = 16; o > 0; o >>= 1) d += __shfl_xor_sync(0xffffffffu, d, o);
        const float nm = fmaxf(m, d);
        const float sc = __expf(m - nm);
        const float p  = __expf(d - nm);
        S = S * sc + p;
        R[0] = R[0] * sc + p * c0.x;
        R[1] = R[1] * sc + p * c0.y;
        R[2] = R[2] * sc + p * c0.z;
        R[3] = R[3] * sc + p * c0.w;
        R[4] = R[4] * sc + p * c1.x;
        R[5] = R[5] * sc + p * c1.y;
        R[6] = R[6] * sc + p * c1.z;
        R[7] = R[7] * sc + p * c1.w;
        m = nm;
        ii = nx; have = hn;
        if (hn) { c0 = n0f; c1 = n1f; }
    }

    if (lane == 0) { mw_s[wid] = m; Sw_s[wid] = S; }
    #pragma unroll
    for (int j = 0; j < 4; j++) {
        Rall[wid][lane * 4 + j]       = R[j];
        Rall[wid][128 + lane * 4 + j] = R[4 + j];
    }
    __syncthreads();

    float r = 0.f;
    if (en > s) {
        float M = mw_s[0];
        #pragma unroll
        for (int w = 1; w < 8; w++) M = fmaxf(M, mw_s[w]);
        float Ss = 0.f, Rs = 0.f;
        #pragma unroll
        for (int w = 0; w < 8; w++) {
            const float f = __expf(mw_s[w] - M);
            Ss += f * Sw_s[w];
            Rs += f * Rall[w][t];
        }
        r = Rs / (Ss + 1e-16f);
    }

    const size_t xb = (size_t)g * XDIM;
    split_bf16(h_s[t], g_x_h[xb + t],          g_x_l[xb + t]);
    split_bf16(r,      g_x_h[xb + HIDDEN + t], g_x_l[xb + HIDDEN + t]);
}

// ---------------- shared MMA helpers ----------------
__device__ __forceinline__ void mma_bf16(float c[4], const uint32_t a[4], const uint32_t b[2]) {
    asm volatile(
        "mma.sync.aligned.m16n8k16.row.col.f32.bf16.bf16.f32 "
        "{%0,%1,%2,%3}, {%4,%5,%6,%7}, {%8,%9}, {%0,%1,%2,%3};\n"
        : "+f"(c[0]), "+f"(c[1]), "+f"(c[2]), "+f"(c[3])
        : "r"(a[0]), "r"(a[1]), "r"(a[2]), "r"(a[3]), "r"(b[0]), "r"(b[1]));
}
__device__ __forceinline__ void cp16(__nv_bfloat16* dst, const __nv_bfloat16* src) {
    uint32_t d = (uint32_t)__cvta_generic_to_shared(dst);
    asm volatile("cp.async.cg.shared.global [%0], [%1], 16;\n" :: "r"(d), "l"(src));
}
__device__ __forceinline__ void ldsm_x4(uint32_t r[4], uint32_t saddr) {
    asm volatile("ldmatrix.sync.aligned.m8n8.x4.shared.b16 {%0,%1,%2,%3}, [%4];"
                 : "=r"(r[0]), "=r"(r[1]), "=r"(r[2]), "=r"(r[3]) : "r"(saddr));
}

// ======== gates GEMM: 128x128 tiles, 2 CTAs/SM, ldmatrix fragments, fused LSTM cell ========
#define GP 40
#define GSZ (128 * GP)
#define G_SMEM_BYTES (2 * 4 * GSZ * 2)   // 81920
#define GCP 132

__global__ void __launch_bounds__(256, 2)
k_gates(const __nv_bfloat16* __restrict__ A_h, const __nv_bfloat16* __restrict__ A_l,
        const __nv_bfloat16* __restrict__ B_h, const __nv_bfloat16* __restrict__ B_l,
        const float* __restrict__ bias) {
    extern __shared__ __nv_bfloat16 sg[];
    __shared__ float sbias[128];

    const int tid  = threadIdx.x;
    const int lane = tid & 31;
    const int wid  = tid >> 5;
    const int wm   = wid & 3;          // 4 warps in M
    const int wn   = wid >> 2;         // 2 warps in N
    const int g8   = lane >> 2;
    const int tg   = lane & 3;
    const int mat  = lane >> 3;        // ldmatrix matrix selector (0..3)
    const int rim  = lane & 7;         // row within matrix

    const int m0 = blockIdx.y * 128;
    const int n0 = blockIdx.x * 128;
    const int dbase = n0 >> 2;

    if (tid < 128) sbias[tid] = bias[n0 + tid];

    // shared base address (bytes, shared state space)
    uint32_t sbase;
    asm("{ .reg .u64 t; cvta.to.shared.u64 t, %1; cvt.u32.u64 %0, t; }"
        : "=r"(sbase) : "l"(sg));

    // ldmatrix thread-constant address offsets (bytes, relative to array start)
    // A x4: mat0 = rows[w..w+7]@k, mat1 = rows[w+8..]@k, mat2 = rows[w..]@k+8, mat3 = rows[w+8..]@k+8
    const uint32_t aoff = ((uint32_t)((wm * 32 + (mat & 1) * 8 + rim) * GP + (mat >> 1) * 8)) * 2;
    // B x4: mat0 = n[in]@k, mat1 = n[in]@k+8, mat2 = n[in+1]@k, mat3 = n[in+1]@k+8
    const uint32_t boff = ((uint32_t)((wn * 64 + (mat >> 1) * 8 + rim) * GP + (mat & 1) * 8)) * 2;

    float acc[2][8][4];
    #pragma unroll
    for (int im = 0; im < 2; im++)
        #pragma unroll
        for (int in = 0; in < 8; in++)
            #pragma unroll
            for (int q = 0; q < 4; q++) acc[im][in][q] = 0.f;

    const int r0 = tid >> 2, q0 = tid & 3;
    const int r1 = (tid + 256) >> 2, q1 = tid & 3;

    auto stage = [&](int t) {
        const int stg = t & 1;
        const int kb = t * 32;
        __nv_bfloat16* base = sg + stg * 4 * GSZ;
        __nv_bfloat16* dAh = base;
        __nv_bfloat16* dAl = base + GSZ;
        __nv_bfloat16* dBh = base + 2 * GSZ;
        __nv_bfloat16* dBl = base + 3 * GSZ;
        cp16(dAh + r0 * GP + q0 * 8, A_h + (size_t)(m0 + r0) * XDIM + kb + q0 * 8);
        cp16(dAh + r1 * GP + q1 * 8, A_h + (size_t)(m0 + r1) * XDIM + kb + q1 * 8);
        cp16(dAl + r0 * GP + q0 * 8, A_l + (size_t)(m0 + r0) * XDIM + kb + q0 * 8);
        cp16(dAl + r1 * GP + q1 * 8, A_l + (size_t)(m0 + r1) * XDIM + kb + q1 * 8);
        cp16(dBh + r0 * GP + q0 * 8, B_h + (size_t)(n0 + r0) * XDIM + kb + q0 * 8);
        cp16(dBh + r1 * GP + q1 * 8, B_h + (size_t)(n0 + r1) * XDIM + kb + q1 * 8);
        cp16(dBl + r0 * GP + q0 * 8, B_l + (size_t)(n0 + r0) * XDIM + kb + q0 * 8);
        cp16(dBl + r1 * GP + q1 * 8, B_l + (size_t)(n0 + r1) * XDIM + kb + q1 * 8);
    };

    stage(0);
    asm volatile("cp.async.commit_group;\n");

    const int T = XDIM / 32;   // 16
    for (int t = 0; t < T; t++) {
        const int stg = t & 1;
        if (t + 1 < T) stage(t + 1);
        asm volatile("cp.async.commit_group;\n");
        asm volatile("cp.async.wait_group 1;\n");
        __syncthreads();

        const uint32_t base = sbase + (uint32_t)(stg * 4 * GSZ) * 2;
        const uint32_t aAh = base + aoff;
        const uint32_t aAl = aAh + (uint32_t)GSZ * 2;
        const uint32_t aBh = base + (uint32_t)(2 * GSZ) * 2 + boff;
        const uint32_t aBl = aBh + (uint32_t)GSZ * 2;

        #pragma unroll
        for (int kk = 0; kk < 32; kk += 16) {
            const uint32_t ko = (uint32_t)kk * 2;
            uint32_t ah[2][4], al[2][4];
            #pragma unroll
            for (int im = 0; im < 2; im++) {
                ldsm_x4(ah[im], aAh + (uint32_t)(im * 16 * GP) * 2 + ko);
                ldsm_x4(al[im], aAl + (uint32_t)(im * 16 * GP) * 2 + ko);
            }
            uint32_t bh[8][2], bl[8][2];
            #pragma unroll
            for (int p = 0; p < 4; p++) {
                uint32_t th[4], tl[4];
                ldsm_x4(th, aBh + (uint32_t)(p * 16 * GP) * 2 + ko);
                ldsm_x4(tl, aBl + (uint32_t)(p * 16 * GP) * 2 + ko);
                bh[2 * p][0] = th[0]; bh[2 * p][1] = th[1];
                bh[2 * p + 1][0] = th[2]; bh[2 * p + 1][1] = th[3];
                bl[2 * p][0] = tl[0]; bl[2 * p][1] = tl[1];
                bl[2 * p + 1][0] = tl[2]; bl[2 * p + 1][1] = tl[3];
            }
            #pragma unroll
            for (int in = 0; in < 8; in++)
                #pragma unroll
                for (int im = 0; im < 2; im++) {
                    mma_bf16(acc[im][in], ah[im], bh[in]);
                    mma_bf16(acc[im][in], ah[im], bl[in]);
                    mma_bf16(acc[im][in], al[im], bh[in]);
                }
        }
        __syncthreads();
    }

    // ---- fused LSTM cell epilogue ----
    float* sC = reinterpret_cast<float*>(sg);
    #pragma unroll
    for (int im = 0; im < 2; im++)
        #pragma unroll
        for (int in = 0; in < 8; in++) {
            const int rl = wm * 32 + im * 16 + g8;
            const int cl = wn * 64 + in * 8 + 2 * tg;
            sC[rl * GCP + cl]           = acc[im][in][0] + sbias[cl];
            sC[rl * GCP + cl + 1]       = acc[im][in][1] + sbias[cl + 1];
            sC[(rl + 8) * GCP + cl]     = acc[im][in][2] + sbias[cl];
            sC[(rl + 8) * GCP + cl + 1] = acc[im][in][3] + sbias[cl + 1];
        }
    __syncthreads();

    #pragma unroll
    for (int it = 0; it < 16; it++) {
        const int idx = tid + it * 256;
        const int row = idx >> 5, dl = idx & 31;
        const float4 gv = *reinterpret_cast<const float4*>(&sC[row * GCP + dl * 4]); // i,f,g,o
        const int gi = m0 + row;
        const int d  = dbase + dl;
        const size_t hb = (size_t)gi * HIDDEN + d;
        const float c_old = g_c[hb];
        const float c_new = sigf(gv.y) * c_old + sigf(gv.x) * tanhf(gv.z);
        const float h_new = sigf(gv.w) * tanhf(c_new);
        g_c[hb] = c_new;
        g_h[hb] = h_new;
        split_bf16(h_new, g_x_h[(size_t)gi * XDIM + d], g_x_l[(size_t)gi * XDIM + d]);
    }
}

// ---------------- generic GEMM for the two MLP launches ----------------
#define BM 64
#define BN 128
#define BK 32
#define PITCH 40
#define SZ_A (64 * PITCH)
#define SZ_B (128 * PITCH)
#define SMEM_HALFS (2 * SZ_A * 2 + 2 * SZ_B * 2)
#define SMEM_BYTES (SMEM_HALFS * 2)

__global__ void __launch_bounds__(256, 3)
k_gemm(const __nv_bfloat16* __restrict__ A_h, const __nv_bfloat16* __restrict__ A_l,
       const __nv_bfloat16* __restrict__ B_h, const __nv_bfloat16* __restrict__ B_l,
       const float* __restrict__ bias,
       float* __restrict__ C, __nv_bfloat16* __restrict__ C_h, __nv_bfloat16* __restrict__ C_l,
       int N, int K, int mode) {
    extern __shared__ __nv_bfloat16 sm[];
    __nv_bfloat16* sA_h = sm;
    __nv_bfloat16* sA_l = sA_h + 2 * SZ_A;
    __nv_bfloat16* sB_h = sA_l + 2 * SZ_A;
    __nv_bfloat16* sB_l = sB_h + 2 * SZ_B;

    const int tid  = threadIdx.x;
    const int lane = tid & 31;
    const int wid  = tid >> 5;
    const int wm   = wid & 1;
    const int wn   = wid >> 1;
    const int g8   = lane >> 2;
    const int tg   = lane & 3;

    const int m0 = blockIdx.y * BM;
    const int n0 = blockIdx.x * BN;
    const int T  = K / BK;

    const int ar = tid >> 2, aq = tid & 3;
    const int br0 = tid >> 2, br1 = (tid + 256) >> 2;

    float acc[2][4][4];
    #pragma unroll
    for (int im = 0; im < 2; im++)
        #pragma unroll
        for (int in = 0; in < 4; in++)
            #pragma unroll
            for (int q = 0; q < 4; q++) acc[im][in][q] = 0.f;

    auto stage = [&](int tile, int stg) {
        const int kb = tile * BK;
        __nv_bfloat16* dAh = sA_h + stg * SZ_A;
        __nv_bfloat16* dAl = sA_l + stg * SZ_A;
        __nv_bfloat16* dBh = sB_h + stg * SZ_B;
        __nv_bfloat16* dBl = sB_l + stg * SZ_B;
        cp16(dAh + ar * PITCH + aq * 8, A_h + (size_t)(m0 + ar) * K + kb + aq * 8);
        cp16(dAl + ar * PITCH + aq * 8, A_l + (size_t)(m0 + ar) * K + kb + aq * 8);
        cp16(dBh + br0 * PITCH + aq * 8, B_h + (size_t)(n0 + br0) * K + kb + aq * 8);
        cp16(dBh + br1 * PITCH + aq * 8, B_h + (size_t)(n0 + br1) * K + kb + aq * 8);
        cp16(dBl + br0 * PITCH + aq * 8, B_l + (size_t)(n0 + br0) * K + kb + aq * 8);
        cp16(dBl + br1 * PITCH + aq * 8, B_l + (size_t)(n0 + br1) * K + kb + aq * 8);
    };

    stage(0, 0);
    asm volatile("cp.async.commit_group;\n");

    for (int t = 0; t < T; t++) {
        const int stg = t & 1;
        if (t + 1 < T) stage(t + 1, (t + 1) & 1);
        asm volatile("cp.async.commit_group;\n");
        asm volatile("cp.async.wait_group 1;\n");
        __syncthreads();

        const __nv_bfloat16* Ah = sA_h + stg * SZ_A;
        const __nv_bfloat16* Al = sA_l + stg * SZ_A;
        const __nv_bfloat16* Bh = sB_h + stg * SZ_B;
        const __nv_bfloat16* Bl = sB_l + stg * SZ_B;

        #pragma unroll
        for (int kk = 0; kk < BK; kk += 16) {
            uint32_t ah[2][4], al[2][4], bh[4][2], bl[4][2];
            #pragma unroll
            for (int im = 0; im < 2; im++) {
                const int r = wm * 32 + im * 16 + g8;
                ah[im][0] = *reinterpret_cast<const uint32_t*>(Ah + r * PITCH + kk + 2 * tg);
                ah[im][1] = *reinterpret_cast<const uint32_t*>(Ah + (r + 8) * PITCH + kk + 2 * tg);
                ah[im][2] = *reinterpret_cast<const uint32_t*>(Ah + r * PITCH + kk + 2 * tg + 8);
                ah[im][3] = *reinterpret_cast<const uint32_t*>(Ah + (r + 8) * PITCH + kk + 2 * tg + 8);
                al[im][0] = *reinterpret_cast<const uint32_t*>(Al + r * PITCH + kk + 2 * tg);
                al[im][1] = *reinterpret_cast<const uint32_t*>(Al + (r + 8) * PITCH + kk + 2 * tg);
                al[im][2] = *reinterpret_cast<const uint32_t*>(Al + r * PITCH + kk + 2 * tg + 8);
                al[im][3] = *reinterpret_cast<const uint32_t*>(Al + (r + 8) * PITCH + kk + 2 * tg + 8);
            }
            #pragma unroll
            for (int in = 0; in < 4; in++) {
                const int rn = wn * 32 + in * 8 + g8;
                bh[in][0] = *reinterpret_cast<const uint32_t*>(Bh + rn * PITCH + kk + 2 * tg);
                bh[in][1] = *reinterpret_cast<const uint32_t*>(Bh + rn * PITCH + kk + 2 * tg + 8);
                bl[in][0] = *reinterpret_cast<const uint32_t*>(Bl + rn * PITCH + kk + 2 * tg);
                bl[in][1] = *reinterpret_cast<const uint32_t*>(Bl + rn * PITCH + kk + 2 * tg + 8);
            }
            #pragma unroll
            for (int im = 0; im < 2; im++)
                #pragma unroll
                for (int in = 0; in < 4; in++) {
                    mma_bf16(acc[im][in], ah[im], bh[in]);
                    mma_bf16(acc[im][in], ah[im], bl[in]);
                    mma_bf16(acc[im][in], al[im], bh[in]);
                }
        }
        __syncthreads();
    }

    #pragma unroll
    for (int im = 0; im < 2; im++) {
        #pragma unroll
        for (int in = 0; in < 4; in++) {
            const int row0 = m0 + wm * 32 + im * 16 + g8;
            const int col  = n0 + wn * 32 + in * 8 + 2 * tg;
            const float b0 = bias[col], b1 = bias[col + 1];
            float v0 = acc[im][in][0] + b0;
            float v1 = acc[im][in][1] + b1;
            float v2 = acc[im][in][2] + b0;
            float v3 = acc[im][in][3] + b1;
            if (mode == 1) {
                v0 = fmaxf(v0, 0.f); v1 = fmaxf(v1, 0.f);
                v2 = fmaxf(v2, 0.f); v3 = fmaxf(v3, 0.f);
                __nv_bfloat16 h0, l0, h1, l1;
                split_bf16(v0, h0, l0); split_bf16(v1, h1, l1);
                *reinterpret_cast<__nv_bfloat162*>(&C_h[(size_t)row0 * N + col]) = __nv_bfloat162(h0, h1);
                *reinterpret_cast<__nv_bfloat162*>(&C_l[(size_t)row0 * N + col]) = __nv_bfloat162(l0, l1);
                split_bf16(v2, h0, l0); split_bf16(v3, h1, l1);
                *reinterpret_cast<__nv_bfloat162*>(&C_h[(size_t)(row0 + 8) * N + col]) = __nv_bfloat162(h0, h1);
                *reinterpret_cast<__nv_bfloat162*>(&C_l[(size_t)(row0 + 8) * N + col]) = __nv_bfloat162(l0, l1);
            } else {
                *reinterpret_cast<float2*>(&C[(size_t)row0 * N + col])       = make_float2(v0, v1);
                *reinterpret_cast<float2*>(&C[(size_t)(row0 + 8) * N + col]) = make_float2(v2, v3);
            }
        }
    }
}

// ---------------- launch ----------------
extern "C" void kernel_launch(void* const* d_in, const int* in_sizes, int n_in,
                              void* d_out, int out_size) {
    const float* emb  = (const float*)d_in[0];
    const int*   bidx = (const int*)d_in[1];
    const float* W_ih = (const float*)d_in[2];
    const float* W_hh = (const float*)d_in[3];
    const float* b_ih = (const float*)d_in[4];
    const float* b_hh = (const float*)d_in[5];
    const float* W1   = (const float*)d_in[6];
    const float* b1   = (const float*)d_in[7];
    const float* W2   = (const float*)d_in[8];
    const float* b2   = (const float*)d_in[9];
    float* out = (float*)d_out;
    const int nn = in_sizes[1];

    float *p_bc;
    __nv_bfloat16 *p_x_h, *p_x_l, *p_hdn_h, *p_hdn_l;
    __nv_bfloat16 *p_Wc_h, *p_Wc_l, *p_W1_h, *p_W1_l, *p_W2_h, *p_W2_l;
    cudaGetSymbolAddress((void**)&p_bc,    g_bc);
    cudaGetSymbolAddress((void**)&p_x_h,   g_x_h);
    cudaGetSymbolAddress((void**)&p_x_l,   g_x_l);
    cudaGetSymbolAddress((void**)&p_hdn_h, g_hdn_h);
    cudaGetSymbolAddress((void**)&p_hdn_l, g_hdn_l);
    cudaGetSymbolAddress((void**)&p_Wc_h,  g_Wc_h);
    cudaGetSymbolAddress((void**)&p_Wc_l,  g_Wc_l);
    cudaGetSymbolAddress((void**)&p_W1_h,  g_W1_h);
    cudaGetSymbolAddress((void**)&p_W1_l,  g_W1_l);
    cudaGetSymbolAddress((void**)&p_W2_h,  g_W2_h);
    cudaGetSymbolAddress((void**)&p_W2_l,  g_W2_l);

    cudaFuncSetAttribute(k_gemm,  cudaFuncAttributeMaxDynamicSharedMemorySize, SMEM_BYTES);
    cudaFuncSetAttribute(k_gates, cudaFuncAttributeMaxDynamicSharedMemorySize, G_SMEM_BYTES);

    k_setup<<<2048, 256>>>(bidx, nn, W_ih, W_hh, b_ih, b_hh, W1, W2);

    for (int s = 0; s < STEPS; s++) {
        k_attention<<<N_GRAPHS, 256>>>(emb);
        k_gates<<<dim3(GATESD / 128, N_GRAPHS / 128), 256, G_SMEM_BYTES>>>(
            p_x_h, p_x_l, p_Wc_h, p_Wc_l, p_bc);
    }

    // MLP readout
    k_gemm<<<dim3(HIDDEN / BN, N_GRAPHS / BM), 256, SMEM_BYTES>>>(
        p_x_h, p_x_l, p_W1_h, p_W1_l, b1, nullptr, p_hdn_h, p_hdn_l,
        HIDDEN, XDIM, 1);
    k_gemm<<<dim3(HIDDEN / BN, N_GRAPHS / BM), 256, SMEM_BYTES>>>(
        p_hdn_h, p_hdn_l, p_W2_h, p_W2_l, b2, out, nullptr, nullptr,
        HIDDEN, HIDDEN, 0);
}